// round 16
// baseline (speedup 1.0000x reference)
#include <cuda_runtime.h>
#include <cuda_bf16.h>
#include <math.h>
#include <stdint.h>
#include <mma.h>

using namespace nvcuda;

#define B_      16
#define T_      2048
#define F_      512
#define C_      256
#define NEG_    10
#define COPIES  11
#define STEPS_  12
#define UB_     8
#define NBLK    ((T_ / UB_) * B_)      // 4096 loss blocks total

#define NCHUNK  4
#define BPC     (B_ / NCHUNK)          // 4 batches per chunk

#define NA_ ((size_t)B_ * T_ * F_)
#define NW_ ((size_t)F_ * C_)

// Scratch (allocation-free rule: __device__ globals)
__device__ __nv_bfloat16       g_tl16[(size_t)B_ * T_ * C_];   // 16 MB
__device__ __nv_bfloat16       g_A16[NA_];                     // 32 MB
__device__ __nv_bfloat16       g_W16[NW_];
__device__ unsigned long long  g_acc;    // Q20 fixed-point loss accumulator
__device__ unsigned int        g_done;   // completed-block counter

// ---------------------------------------------------------------------------
// Fork-join stream resources, created at load time (before harness memory
// checkpoints). Work per kernel_launch call is identical every call.
// ---------------------------------------------------------------------------
struct StreamRes {
    cudaStream_t s2;
    cudaEvent_t  evG[NCHUNK];
    cudaEvent_t  evJoin;
    StreamRes() {
        cudaStreamCreateWithFlags(&s2, cudaStreamNonBlocking);
        for (int i = 0; i < NCHUNK; i++)
            cudaEventCreateWithFlags(&evG[i], cudaEventDisableTiming);
        cudaEventCreateWithFlags(&evJoin, cudaEventDisableTiming);
    }
};
static StreamRes g_res;

// ---------------------------------------------------------------------------
__device__ __forceinline__ uint32_t smem_u32(const void* p) {
    uint32_t a;
    asm("{ .reg .u64 t; cvta.to.shared.u64 t, %1; cvt.u32.u64 %0, t; }"
        : "=r"(a) : "l"(p));
    return a;
}
__device__ __forceinline__ void cp16(uint32_t dst, const void* src) {
    asm volatile("cp.async.cg.shared.global [%0], [%1], 16;"
                 :: "r"(dst), "l"(src) : "memory");
}
__device__ __forceinline__ void cp_commit() {
    asm volatile("cp.async.commit_group;" ::: "memory");
}
__device__ __forceinline__ void cp_wait1() {
    asm volatile("cp.async.wait_group 1;" ::: "memory");
}
__device__ __forceinline__ void cp_wait0() {
    asm volatile("cp.async.wait_group 0;" ::: "memory");
}

// ---------------------------------------------------------------------------
// Kernel 0: fp32 -> bf16 (RN) for A and W.
// ---------------------------------------------------------------------------
__global__ void __launch_bounds__(256) convert_bf16(
    const float* __restrict__ A, const float* __restrict__ W)
{
    const size_t nA4 = NA_ / 4, nW4 = NW_ / 4;
    const size_t stride = (size_t)gridDim.x * blockDim.x;
    for (size_t i = (size_t)blockIdx.x * blockDim.x + threadIdx.x;
         i < nA4 + nW4; i += stride) {
        union { __nv_bfloat162 h2[2]; uint2 u; } pk;
        if (i < nA4) {
            float4 v = ((const float4*)A)[i];
            pk.h2[0] = __float22bfloat162_rn(make_float2(v.x, v.y));
            pk.h2[1] = __float22bfloat162_rn(make_float2(v.z, v.w));
            ((uint2*)g_A16)[i] = pk.u;
        } else {
            size_t j = i - nA4;
            float4 v = ((const float4*)W)[j];
            pk.h2[0] = __float22bfloat162_rn(make_float2(v.x, v.y));
            pk.h2[1] = __float22bfloat162_rn(make_float2(v.z, v.w));
            ((uint2*)g_W16)[j] = pk.u;
        }
    }
}

// ---------------------------------------------------------------------------
// Kernel A: tl = A16 @ W16 + bl via BF16 wmma, fp32 acc, bf16 output.
// Tile 64x128, warp tile 32x32, 3-stage cp.async (distance-2 writes).
// by0 = M-block offset for batch-chunked launches.
// ---------------------------------------------------------------------------
#define GKC     32
#define SA_LD   40
#define SB_LD   136
#define SA_SZ   (64 * SA_LD)
#define SB_SZ   (GKC * SB_LD)
#define DYN_SM  (3 * (SA_SZ + SB_SZ) * sizeof(__nv_bfloat16))

__global__ void __launch_bounds__(256, 3) gemm_tl_tc(
    const float* __restrict__ bias, int by0)
{
    extern __shared__ __nv_bfloat16 dynb[];
    __nv_bfloat16* sA = dynb;                 // [3][SA_SZ]
    __nv_bfloat16* sB = dynb + 3 * SA_SZ;     // [3][SB_SZ]
    __shared__ float epi[8][16 * 20];
    __shared__ float bias_s[128];

    const int tid  = threadIdx.x;
    const int bx   = blockIdx.x;
    const int by   = by0 + blockIdx.y;
    const int wid  = tid >> 5;
    const int lane = tid & 31;
    const int wm   = wid & 1;
    const int wn   = wid >> 1;

    if (tid < 128) bias_s[tid] = bias[bx * 128 + tid];

    wmma::fragment<wmma::accumulator, 16, 16, 16, float> acc[2][2];
#pragma unroll
    for (int i = 0; i < 2; i++)
#pragma unroll
        for (int j = 0; j < 2; j++) wmma::fill_fragment(acc[i][j], 0.f);

    const __nv_bfloat16* Abase = g_A16 + (size_t)(by * 64) * F_;
    const __nv_bfloat16* Wbase = g_W16 + bx * 128;

    const uint32_t sAu = smem_u32(sA);
    const uint32_t sBu = smem_u32(sB);

    const int arow = tid >> 2;
    const int acol = (tid & 3) << 3;
    const uint32_t dA = sAu + (uint32_t)(arow * SA_LD + acol) * 2u;
    uint32_t dB[2];
    int brow[2], bcol[2];
#pragma unroll
    for (int q = 0; q < 2; q++) {
        int idx = tid + q * 256;
        brow[q] = idx >> 4;  bcol[q] = (idx & 15) << 3;
        dB[q] = sBu + (uint32_t)(brow[q] * SB_LD + bcol[q]) * 2u;
    }

    auto issue_tile = [&](int k0, int s) {
        cp16(dA + (uint32_t)s * SA_SZ * 2u,
             Abase + (size_t)arow * F_ + k0 + acol);
        uint32_t oB = (uint32_t)s * SB_SZ * 2u;
#pragma unroll
        for (int q = 0; q < 2; q++)
            cp16(dB[q] + oB, Wbase + (size_t)(k0 + brow[q]) * C_ + bcol[q]);
        cp_commit();
    };

    issue_tile(0, 0);
    issue_tile(GKC, 1);

    const int NIT = F_ / GKC;   // 16
    for (int it = 0; it < NIT; ++it) {
        if (it + 1 < NIT) cp_wait1(); else cp_wait0();
        __syncthreads();

        if (it + 2 < NIT)
            issue_tile((it + 2) * GKC, (it + 2) % 3);

        const __nv_bfloat16* cA = sA + (it % 3) * SA_SZ;
        const __nv_bfloat16* cB = sB + (it % 3) * SB_SZ;
#pragma unroll
        for (int ks = 0; ks < 2; ks++) {
            wmma::fragment<wmma::matrix_a, 16, 16, 16, __nv_bfloat16, wmma::row_major> af[2];
            wmma::fragment<wmma::matrix_b, 16, 16, 16, __nv_bfloat16, wmma::row_major> bf[2];
#pragma unroll
            for (int i = 0; i < 2; i++)
                wmma::load_matrix_sync(af[i], cA + (wm * 32 + i * 16) * SA_LD + ks * 16, SA_LD);
#pragma unroll
            for (int j = 0; j < 2; j++)
                wmma::load_matrix_sync(bf[j], cB + (ks * 16) * SB_LD + wn * 32 + j * 16, SB_LD);
#pragma unroll
            for (int i = 0; i < 2; i++)
#pragma unroll
                for (int j = 0; j < 2; j++)
                    wmma::mma_sync(acc[i][j], af[i], bf[j], acc[i][j]);
        }
    }
    __syncthreads();

    const int row_l = lane >> 1;
    const int col_l = (lane & 1) * 8;
#pragma unroll
    for (int i = 0; i < 2; i++) {
#pragma unroll
        for (int j = 0; j < 2; j++) {
            wmma::store_matrix_sync(&epi[wid][0], acc[i][j], 20, wmma::mem_row_major);
            __syncwarp();
            int grow = by * 64 + wm * 32 + i * 16 + row_l;
            int bl0  = wn * 32 + j * 16 + col_l;
            int gcol = bx * 128 + bl0;
            const float* er = &epi[wid][row_l * 20 + col_l];
            union { __nv_bfloat162 h2[4]; uint4 u; } pk;
#pragma unroll
            for (int q = 0; q < 4; q++)
                pk.h2[q] = __float22bfloat162_rn(
                    make_float2(er[2 * q] + bias_s[bl0 + 2 * q],
                                er[2 * q + 1] + bias_s[bl0 + 2 * q + 1]));
            *(uint4*)&g_tl16[(size_t)grow * C_ + gcol] = pk.u;
            __syncwarp();
        }
    }
}

// ---------------------------------------------------------------------------
// Kernel B: loss via per-warp 16x16x256 wmma (2-acc ILP). b0 = batch offset.
// ---------------------------------------------------------------------------
#define LDT      264
#define CTXROWS  24
#define TGTROWS  (UB_ * COPIES + 5)         // 93
#define DYN_LOSS ((CTXROWS + TGTROWS) * LDT * sizeof(__nv_bfloat16))
#define Q_SCALE  1048576.0f                 // 2^20

__global__ void __launch_bounds__(256) loss_kernel(
    const float* __restrict__ ctx,   // [B, T, C]
    const float* __restrict__ Ws,    // [12]
    const float* __restrict__ bs,    // [12]
    const int*   __restrict__ neg,   // [B, NEG, T]
    float*       __restrict__ out,
    int b0)
{
    extern __shared__ __nv_bfloat16 dynls[];
    __nv_bfloat16* ctx_s = dynls;                   // [CTXROWS][LDT]
    __nv_bfloat16* tgt_s = dynls + CTXROWS * LDT;   // [TGTROWS][LDT]
    __shared__ float epi[UB_][16 * 20];
    __shared__ float sums_s[UB_][16];
    __shared__ float ws_s[STEPS_], bs_s[STEPS_];
    __shared__ float wsum_s[UB_];

    const int b   = b0 + blockIdx.y;
    const int u0  = blockIdx.x * UB_;
    const int tid = threadIdx.x;
    const int warp = tid >> 5, lane = tid & 31;
    const int u = u0 + warp;
    const unsigned FULL = 0xffffffffu;

    if (tid < STEPS_) { ws_s[tid] = Ws[tid]; bs_s[tid] = bs[tid]; }

    // 1) Issue all 11 gather LDG.128 into registers FIRST.
    uint4 gv[COPIES];
#pragma unroll
    for (int n = 0; n < COPIES; n++) {
        int r = (n == 0) ? u : neg[((size_t)b * NEG_ + (n - 1)) * T_ + u];
        gv[n] = *(const uint4*)(g_tl16 + ((size_t)b * T_ + r) * C_ + lane * 8);
    }

    // 2) ctx window rows 0..18: row j = ctx[b, u0-11+j], fp32 -> bf16.
    for (int idx = tid; idx < 19 * (C_ / 4); idx += 256) {
        int j  = idx / (C_ / 4);
        int c4 = (idx % (C_ / 4)) * 4;
        int gr = u0 - 11 + j;
        float4 v = make_float4(0.f, 0.f, 0.f, 0.f);
        if (gr >= 0)
            v = *(const float4*)(ctx + ((size_t)b * T_ + gr) * C_ + c4);
        union { __nv_bfloat162 h2[2]; uint2 u; } pk;
        pk.h2[0] = __float22bfloat162_rn(make_float2(v.x, v.y));
        pk.h2[1] = __float22bfloat162_rn(make_float2(v.z, v.w));
        *(uint2*)(ctx_s + j * LDT + c4) = pk.u;
    }
    __syncthreads();

    // 3) Write target rows to smem; fuse per-row sums from the same registers.
    float vs[16];
#pragma unroll
    for (int n = 0; n < 16; n++) vs[n] = 0.f;
#pragma unroll
    for (int n = 0; n < COPIES; n++) {
        union { uint4 u4; __nv_bfloat162 h2[4]; } v;
        v.u4 = gv[n];
        float s = 0.f;
#pragma unroll
        for (int q = 0; q < 4; q++) {
            float2 f = __bfloat1622float2(v.h2[q]);
            s += f.x + f.y;
        }
        vs[n] = s;
        *(uint4*)(tgt_s + (warp * COPIES + n) * LDT + lane * 8) = v.u4;
    }

    // Folded 16-value reduction (17 shfl).
    {
        float t8[8], t4[4], t2[2], r;
#pragma unroll
        for (int j = 0; j < 8; j++) {
            float send = (lane & 16) ? vs[j] : vs[8 + j];
            float keep = (lane & 16) ? vs[8 + j] : vs[j];
            t8[j] = keep + __shfl_xor_sync(FULL, send, 16);
        }
#pragma unroll
        for (int j = 0; j < 4; j++) {
            float send = (lane & 8) ? t8[j] : t8[4 + j];
            float keep = (lane & 8) ? t8[4 + j] : t8[j];
            t4[j] = keep + __shfl_xor_sync(FULL, send, 8);
        }
#pragma unroll
        for (int j = 0; j < 2; j++) {
            float send = (lane & 4) ? t4[j] : t4[2 + j];
            float keep = (lane & 4) ? t4[2 + j] : t4[j];
            t2[j] = keep + __shfl_xor_sync(FULL, send, 4);
        }
        {
            float send = (lane & 2) ? t2[0] : t2[1];
            float keep = (lane & 2) ? t2[1] : t2[0];
            r = keep + __shfl_xor_sync(FULL, send, 2);
        }
        r += __shfl_xor_sync(FULL, r, 1);
        if (lane < 22 && (lane & 1) == 0)
            sums_s[warp][lane >> 1] = r;
    }
    __syncwarp();

    // 4) 16x16x256 wmma chain, 2 independent accumulators.
    wmma::fragment<wmma::accumulator, 16, 16, 16, float> acc0, acc1;
    wmma::fill_fragment(acc0, 0.f);
    wmma::fill_fragment(acc1, 0.f);
    const __nv_bfloat16* Abase = ctx_s + warp * LDT;
    const __nv_bfloat16* Bbase = tgt_s + (warp * COPIES) * LDT;
#pragma unroll
    for (int ks = 0; ks < C_ / 32; ks++) {
        wmma::fragment<wmma::matrix_a, 16, 16, 16, __nv_bfloat16, wmma::row_major> af0, af1;
        wmma::fragment<wmma::matrix_b, 16, 16, 16, __nv_bfloat16, wmma::col_major> bf0, bf1;
        wmma::load_matrix_sync(af0, Abase + (2 * ks) * 16, LDT);
        wmma::load_matrix_sync(bf0, Bbase + (2 * ks) * 16, LDT);
        wmma::load_matrix_sync(af1, Abase + (2 * ks + 1) * 16, LDT);
        wmma::load_matrix_sync(bf1, Bbase + (2 * ks + 1) * 16, LDT);
        wmma::mma_sync(acc0, af0, bf0, acc0);
        wmma::mma_sync(acc1, af1, bf1, acc1);
    }
#pragma unroll
    for (int e = 0; e < acc0.num_elements; e++) acc0.x[e] += acc1.x[e];
    wmma::store_matrix_sync(&epi[warp][0], acc0, 20, wmma::mem_row_major);
    __syncwarp();

    // 5) LSE: lane m (0..11) handles step i = 11-m; valid when i <= u.
    float local = 0.f;
    if (lane < STEPS_) {
        const int m = lane, i = 11 - m;
        if (i <= u) {
            const float* row = &epi[warp][m * 20];
            const float w = ws_s[i], bb = bs_s[i];
            float lv[COPIES];
            float mx;
#pragma unroll
            for (int n = 0; n < COPIES; n++) {
                lv[n] = w * row[n] + bb * sums_s[warp][n];
                mx = (n == 0) ? lv[0] : fmaxf(mx, lv[n]);
            }
            float se = 0.f;
#pragma unroll
            for (int n = 0; n < COPIES; n++) se += expf(lv[n] - mx);
            local = mx + logf(se) - lv[0];
        }
    }

#pragma unroll
    for (int o = 16; o; o >>= 1) local += __shfl_xor_sync(FULL, local, o);
    if (lane == 0) wsum_s[warp] = local;
    __syncthreads();

    // 6) Deterministic fixed-point reduction; last block (across all chunk
    //    launches) finalizes + resets for graph replay.
    if (tid == 0) {
        float s = 0.f;
#pragma unroll
        for (int w = 0; w < UB_; w++) s += wsum_s[w];
        unsigned long long q = (unsigned long long)(long long)llrintf(s * Q_SCALE);
        atomicAdd(&g_acc, q);
        __threadfence();
        unsigned int done = atomicAdd(&g_done, 1u);
        if (done == NBLK - 1) {
            unsigned long long tot = atomicExch(&g_acc, 0ULL);
            atomicExch(&g_done, 0u);
            out[0] = (float)((double)(long long)tot / (double)Q_SCALE);
        }
    }
}

// ---------------------------------------------------------------------------
extern "C" void kernel_launch(void* const* d_in, const int* in_sizes, int n_in,
                              void* d_out, int out_size) {
    const float* true_latent = (const float*)d_in[0];   // [B,T,F]
    const float* ctx         = (const float*)d_in[1];   // [B,T,C]
    const float* Wl          = (const float*)d_in[2];   // [F,C]
    const float* bl          = (const float*)d_in[3];   // [C]
    const float* Ws          = (const float*)d_in[4];   // [12]
    const float* bs          = (const float*)d_in[5];   // [12]
    const int*   neg         = (const int*)d_in[6];     // [B,NEG,T]
    float* out = (float*)d_out;

    cudaFuncSetAttribute(gemm_tl_tc, cudaFuncAttributeMaxDynamicSharedMemorySize,
                         (int)DYN_SM);
    cudaFuncSetAttribute(loss_kernel, cudaFuncAttributeMaxDynamicSharedMemorySize,
                         (int)DYN_LOSS);

    // Stream 0: convert, then GEMM chunks (one event per chunk).
    convert_bf16<<<2048, 256>>>(true_latent, Wl);

    const int byPerChunk = (BPC * T_) / 64;          // 128 M-blocks per chunk
    for (int c = 0; c < NCHUNK; c++) {
        gemm_tl_tc<<<dim3(C_ / 128, byPerChunk), 256, DYN_SM>>>(bl, c * byPerChunk);
        cudaEventRecord(g_res.evG[c], 0);
    }

    // Stream s2: loss chunk c waits only on gemm chunk c.
    for (int c = 0; c < NCHUNK; c++) {
        cudaStreamWaitEvent(g_res.s2, g_res.evG[c], 0);
        loss_kernel<<<dim3(T_ / UB_, BPC), 256, DYN_LOSS, g_res.s2>>>(
            ctx, Ws, bs, neg, out, c * BPC);
    }

    // Join back to stream 0.
    cudaEventRecord(g_res.evJoin, g_res.s2);
    cudaStreamWaitEvent(0, g_res.evJoin, 0);
}

// round 17
// speedup vs baseline: 1.0783x; 1.0783x over previous
#include <cuda_runtime.h>
#include <cuda_bf16.h>
#include <math.h>
#include <stdint.h>
#include <mma.h>

using namespace nvcuda;

#define B_      16
#define T_      2048
#define F_      512
#define C_      256
#define NEG_    10
#define COPIES  11
#define STEPS_  12
#define UB_     8
#define NBLK    ((T_ / UB_) * B_)      // 4096 loss blocks

#define NA_ ((size_t)B_ * T_ * F_)
#define NW_ ((size_t)F_ * C_)

// Scratch (allocation-free rule: __device__ globals)
__device__ __nv_bfloat16       g_tl16[(size_t)B_ * T_ * C_];   // 16 MB
__device__ __nv_bfloat16       g_A16[NA_];                     // 32 MB
__device__ __nv_bfloat16       g_W16[NW_];
__device__ unsigned long long  g_acc;    // Q20 fixed-point loss accumulator
__device__ unsigned int        g_done;   // completed-block counter

// ---------------------------------------------------------------------------
__device__ __forceinline__ uint32_t smem_u32(const void* p) {
    uint32_t a;
    asm("{ .reg .u64 t; cvta.to.shared.u64 t, %1; cvt.u32.u64 %0, t; }"
        : "=r"(a) : "l"(p));
    return a;
}
__device__ __forceinline__ void cp16(uint32_t dst, const void* src) {
    asm volatile("cp.async.cg.shared.global [%0], [%1], 16;"
                 :: "r"(dst), "l"(src) : "memory");
}
__device__ __forceinline__ void cp_commit() {
    asm volatile("cp.async.commit_group;" ::: "memory");
}
__device__ __forceinline__ void cp_wait3() {
    asm volatile("cp.async.wait_group 3;" ::: "memory");
}

// ---------------------------------------------------------------------------
// Kernel 0: fp32 -> bf16 (RN) for A and W.
// ---------------------------------------------------------------------------
__global__ void __launch_bounds__(256) convert_bf16(
    const float* __restrict__ A, const float* __restrict__ W)
{
    const size_t nA4 = NA_ / 4, nW4 = NW_ / 4;
    const size_t stride = (size_t)gridDim.x * blockDim.x;
    for (size_t i = (size_t)blockIdx.x * blockDim.x + threadIdx.x;
         i < nA4 + nW4; i += stride) {
        union { __nv_bfloat162 h2[2]; uint2 u; } pk;
        if (i < nA4) {
            float4 v = ((const float4*)A)[i];
            pk.h2[0] = __float22bfloat162_rn(make_float2(v.x, v.y));
            pk.h2[1] = __float22bfloat162_rn(make_float2(v.z, v.w));
            ((uint2*)g_A16)[i] = pk.u;
        } else {
            size_t j = i - nA4;
            float4 v = ((const float4*)W)[j];
            pk.h2[0] = __float22bfloat162_rn(make_float2(v.x, v.y));
            pk.h2[1] = __float22bfloat162_rn(make_float2(v.z, v.w));
            ((uint2*)g_W16)[j] = pk.u;
        }
    }
}

// ---------------------------------------------------------------------------
// Kernel A: tl = A16 @ W16 + bl via BF16 wmma, fp32 acc, bf16 output.
// Tile 64x128, warp tile 32x32, 5-stage cp.async ring, prefetch distance 4,
// empty-commit padding -> constant wait_group 3. Epilogue aliases dyn smem.
// ---------------------------------------------------------------------------
#define GKC     32
#define NSTG    5
#define SA_LD   40
#define SB_LD   136
#define SA_SZ   (64 * SA_LD)
#define SB_SZ   (GKC * SB_LD)
#define STG_SZ  (SA_SZ + SB_SZ)
#define DYN_SM  (NSTG * STG_SZ * sizeof(__nv_bfloat16))

__global__ void __launch_bounds__(256, 3) gemm_tl_tc(
    const float* __restrict__ bias)  // [C]
{
    extern __shared__ __nv_bfloat16 dynb[];
    __nv_bfloat16* sA = dynb;                      // [NSTG][SA_SZ]
    __nv_bfloat16* sB = dynb + NSTG * SA_SZ;       // [NSTG][SB_SZ]
    __shared__ float bias_s[128];

    const int tid  = threadIdx.x;
    const int bx   = blockIdx.x;   // N tile (0..1)
    const int by   = blockIdx.y;   // M tile (0..511)
    const int wid  = tid >> 5;
    const int lane = tid & 31;
    const int wm   = wid & 1;
    const int wn   = wid >> 1;

    if (tid < 128) bias_s[tid] = bias[bx * 128 + tid];

    wmma::fragment<wmma::accumulator, 16, 16, 16, float> acc[2][2];
#pragma unroll
    for (int i = 0; i < 2; i++)
#pragma unroll
        for (int j = 0; j < 2; j++) wmma::fill_fragment(acc[i][j], 0.f);

    const __nv_bfloat16* Abase = g_A16 + (size_t)(by * 64) * F_;
    const __nv_bfloat16* Wbase = g_W16 + bx * 128;

    const uint32_t sAu = smem_u32(sA);
    const uint32_t sBu = smem_u32(sB);

    // A tile: 64 x 32 bf16 = 256 8-elem chunks -> 1 per thread.
    const int arow = tid >> 2;
    const int acol = (tid & 3) << 3;
    const uint32_t dA = sAu + (uint32_t)(arow * SA_LD + acol) * 2u;
    // B tile: 32 x 128 = 512 chunks -> 2 per thread.
    uint32_t dB[2];
    int brow[2], bcol[2];
#pragma unroll
    for (int q = 0; q < 2; q++) {
        int idx = tid + q * 256;
        brow[q] = idx >> 4;  bcol[q] = (idx & 15) << 3;
        dB[q] = sBu + (uint32_t)(brow[q] * SB_LD + bcol[q]) * 2u;
    }

    auto issue_tile = [&](int k0, int s) {
        cp16(dA + (uint32_t)s * SA_SZ * 2u,
             Abase + (size_t)arow * F_ + k0 + acol);
        uint32_t oB = (uint32_t)s * SB_SZ * 2u;
#pragma unroll
        for (int q = 0; q < 2; q++)
            cp16(dB[q] + oB, Wbase + (size_t)(k0 + brow[q]) * C_ + bcol[q]);
        cp_commit();
    };

    // Prologue: tiles 0..3 in flight (4 groups).
    issue_tile(0, 0);
    issue_tile(1 * GKC, 1);
    issue_tile(2 * GKC, 2);
    issue_tile(3 * GKC, 3);

    const int NIT = F_ / GKC;   // 16
    for (int it = 0; it < NIT; ++it) {
        cp_wait3();            // one group per iter -> tile(it) complete
        __syncthreads();       // visible to all; compute(it-1) finished

        if (it + 4 < NIT)
            issue_tile((it + 4) * GKC, (it + 4) % NSTG);  // stage freed at it-1
        else
            cp_commit();       // empty group keeps the bookkeeping constant

        const __nv_bfloat16* cA = sA + (it % NSTG) * SA_SZ;
        const __nv_bfloat16* cB = sB + (it % NSTG) * SB_SZ;
#pragma unroll
        for (int ks = 0; ks < 2; ks++) {
            wmma::fragment<wmma::matrix_a, 16, 16, 16, __nv_bfloat16, wmma::row_major> af[2];
            wmma::fragment<wmma::matrix_b, 16, 16, 16, __nv_bfloat16, wmma::row_major> bf[2];
#pragma unroll
            for (int i = 0; i < 2; i++)
                wmma::load_matrix_sync(af[i], cA + (wm * 32 + i * 16) * SA_LD + ks * 16, SA_LD);
#pragma unroll
            for (int j = 0; j < 2; j++)
                wmma::load_matrix_sync(bf[j], cB + (ks * 16) * SB_LD + wn * 32 + j * 16, SB_LD);
#pragma unroll
            for (int i = 0; i < 2; i++)
#pragma unroll
                for (int j = 0; j < 2; j++)
                    wmma::mma_sync(acc[i][j], af[i], bf[j], acc[i][j]);
        }
    }
    __syncthreads();

    // Epilogue: alias the (now idle) dynamic buffer as per-warp fp32 bounce.
    float* epi = (float*)dynb + wid * 320;   // 8 warps x 320 floats = 10 KB
    const int row_l = lane >> 1;
    const int col_l = (lane & 1) * 8;
#pragma unroll
    for (int i = 0; i < 2; i++) {
#pragma unroll
        for (int j = 0; j < 2; j++) {
            wmma::store_matrix_sync(epi, acc[i][j], 20, wmma::mem_row_major);
            __syncwarp();
            int grow = by * 64 + wm * 32 + i * 16 + row_l;
            int bl0  = wn * 32 + j * 16 + col_l;
            int gcol = bx * 128 + bl0;
            const float* er = epi + row_l * 20 + col_l;
            union { __nv_bfloat162 h2[4]; uint4 u; } pk;
#pragma unroll
            for (int q = 0; q < 4; q++)
                pk.h2[q] = __float22bfloat162_rn(
                    make_float2(er[2 * q] + bias_s[bl0 + 2 * q],
                                er[2 * q + 1] + bias_s[bl0 + 2 * q + 1]));
            *(uint4*)&g_tl16[(size_t)grow * C_ + gcol] = pk.u;
            __syncwarp();
        }
    }
}

// ---------------------------------------------------------------------------
// Kernel B: loss via per-warp 16x16x256 wmma (2-acc ILP), register-prefetched
// gathers, fused row-sums, fixed-point last-block reduction.
// ---------------------------------------------------------------------------
#define LDT      264
#define CTXROWS  24
#define TGTROWS  (UB_ * COPIES + 5)         // 93
#define DYN_LOSS ((CTXROWS + TGTROWS) * LDT * sizeof(__nv_bfloat16))
#define Q_SCALE  1048576.0f                 // 2^20

__global__ void __launch_bounds__(256) loss_kernel(
    const float* __restrict__ ctx,   // [B, T, C]
    const float* __restrict__ Ws,    // [12]
    const float* __restrict__ bs,    // [12]
    const int*   __restrict__ neg,   // [B, NEG, T]
    float*       __restrict__ out)
{
    extern __shared__ __nv_bfloat16 dynls[];
    __nv_bfloat16* ctx_s = dynls;                   // [CTXROWS][LDT]
    __nv_bfloat16* tgt_s = dynls + CTXROWS * LDT;   // [TGTROWS][LDT]
    __shared__ float epi[UB_][16 * 20];
    __shared__ float sums_s[UB_][16];
    __shared__ float ws_s[STEPS_], bs_s[STEPS_];
    __shared__ float wsum_s[UB_];

    const int b   = blockIdx.y;
    const int u0  = blockIdx.x * UB_;
    const int tid = threadIdx.x;
    const int warp = tid >> 5, lane = tid & 31;
    const int u = u0 + warp;
    const unsigned FULL = 0xffffffffu;

    if (tid < STEPS_) { ws_s[tid] = Ws[tid]; bs_s[tid] = bs[tid]; }

    // 1) Issue all 11 gather LDG.128 into registers FIRST.
    uint4 gv[COPIES];
#pragma unroll
    for (int n = 0; n < COPIES; n++) {
        int r = (n == 0) ? u : neg[((size_t)b * NEG_ + (n - 1)) * T_ + u];
        gv[n] = *(const uint4*)(g_tl16 + ((size_t)b * T_ + r) * C_ + lane * 8);
    }

    // 2) ctx window rows 0..18: row j = ctx[b, u0-11+j], fp32 -> bf16.
    for (int idx = tid; idx < 19 * (C_ / 4); idx += 256) {
        int j  = idx / (C_ / 4);
        int c4 = (idx % (C_ / 4)) * 4;
        int gr = u0 - 11 + j;
        float4 v = make_float4(0.f, 0.f, 0.f, 0.f);
        if (gr >= 0)
            v = *(const float4*)(ctx + ((size_t)b * T_ + gr) * C_ + c4);
        union { __nv_bfloat162 h2[2]; uint2 u; } pk;
        pk.h2[0] = __float22bfloat162_rn(make_float2(v.x, v.y));
        pk.h2[1] = __float22bfloat162_rn(make_float2(v.z, v.w));
        *(uint2*)(ctx_s + j * LDT + c4) = pk.u;
    }
    __syncthreads();

    // 3) Write target rows to smem; fuse per-row sums from the same registers.
    float vs[16];
#pragma unroll
    for (int n = 0; n < 16; n++) vs[n] = 0.f;
#pragma unroll
    for (int n = 0; n < COPIES; n++) {
        union { uint4 u4; __nv_bfloat162 h2[4]; } v;
        v.u4 = gv[n];
        float s = 0.f;
#pragma unroll
        for (int q = 0; q < 4; q++) {
            float2 f = __bfloat1622float2(v.h2[q]);
            s += f.x + f.y;
        }
        vs[n] = s;
        *(uint4*)(tgt_s + (warp * COPIES + n) * LDT + lane * 8) = v.u4;
    }

    // Folded 16-value reduction (17 shfl).
    {
        float t8[8], t4[4], t2[2], r;
#pragma unroll
        for (int j = 0; j < 8; j++) {
            float send = (lane & 16) ? vs[j] : vs[8 + j];
            float keep = (lane & 16) ? vs[8 + j] : vs[j];
            t8[j] = keep + __shfl_xor_sync(FULL, send, 16);
        }
#pragma unroll
        for (int j = 0; j < 4; j++) {
            float send = (lane & 8) ? t8[j] : t8[4 + j];
            float keep = (lane & 8) ? t8[4 + j] : t8[j];
            t4[j] = keep + __shfl_xor_sync(FULL, send, 8);
        }
#pragma unroll
        for (int j = 0; j < 2; j++) {
            float send = (lane & 4) ? t4[j] : t4[2 + j];
            float keep = (lane & 4) ? t4[2 + j] : t4[j];
            t2[j] = keep + __shfl_xor_sync(FULL, send, 4);
        }
        {
            float send = (lane & 2) ? t2[0] : t2[1];
            float keep = (lane & 2) ? t2[1] : t2[0];
            r = keep + __shfl_xor_sync(FULL, send, 2);
        }
        r += __shfl_xor_sync(FULL, r, 1);
        if (lane < 22 && (lane & 1) == 0)
            sums_s[warp][lane >> 1] = r;
    }
    __syncwarp();

    // 4) 16x16x256 wmma chain, 2 independent accumulators.
    wmma::fragment<wmma::accumulator, 16, 16, 16, float> acc0, acc1;
    wmma::fill_fragment(acc0, 0.f);
    wmma::fill_fragment(acc1, 0.f);
    const __nv_bfloat16* Abase = ctx_s + warp * LDT;
    const __nv_bfloat16* Bbase = tgt_s + (warp * COPIES) * LDT;
#pragma unroll
    for (int ks = 0; ks < C_ / 32; ks++) {
        wmma::fragment<wmma::matrix_a, 16, 16, 16, __nv_bfloat16, wmma::row_major> af0, af1;
        wmma::fragment<wmma::matrix_b, 16, 16, 16, __nv_bfloat16, wmma::col_major> bf0, bf1;
        wmma::load_matrix_sync(af0, Abase + (2 * ks) * 16, LDT);
        wmma::load_matrix_sync(bf0, Bbase + (2 * ks) * 16, LDT);
        wmma::load_matrix_sync(af1, Abase + (2 * ks + 1) * 16, LDT);
        wmma::load_matrix_sync(bf1, Bbase + (2 * ks + 1) * 16, LDT);
        wmma::mma_sync(acc0, af0, bf0, acc0);
        wmma::mma_sync(acc1, af1, bf1, acc1);
    }
#pragma unroll
    for (int e = 0; e < acc0.num_elements; e++) acc0.x[e] += acc1.x[e];
    wmma::store_matrix_sync(&epi[warp][0], acc0, 20, wmma::mem_row_major);
    __syncwarp();

    // 5) LSE: lane m (0..11) handles step i = 11-m; valid when i <= u.
    float local = 0.f;
    if (lane < STEPS_) {
        const int m = lane, i = 11 - m;
        if (i <= u) {
            const float* row = &epi[warp][m * 20];
            const float w = ws_s[i], bb = bs_s[i];
            float lv[COPIES];
            float mx;
#pragma unroll
            for (int n = 0; n < COPIES; n++) {
                lv[n] = w * row[n] + bb * sums_s[warp][n];
                mx = (n == 0) ? lv[0] : fmaxf(mx, lv[n]);
            }
            float se = 0.f;
#pragma unroll
            for (int n = 0; n < COPIES; n++) se += expf(lv[n] - mx);
            local = mx + logf(se) - lv[0];
        }
    }

#pragma unroll
    for (int o = 16; o; o >>= 1) local += __shfl_xor_sync(FULL, local, o);
    if (lane == 0) wsum_s[warp] = local;
    __syncthreads();

    // 6) Deterministic fixed-point reduction; last block finalizes + resets.
    if (tid == 0) {
        float s = 0.f;
#pragma unroll
        for (int w = 0; w < UB_; w++) s += wsum_s[w];
        unsigned long long q = (unsigned long long)(long long)llrintf(s * Q_SCALE);
        atomicAdd(&g_acc, q);
        __threadfence();
        unsigned int done = atomicAdd(&g_done, 1u);
        if (done == NBLK - 1) {
            unsigned long long tot = atomicExch(&g_acc, 0ULL);
            atomicExch(&g_done, 0u);
            out[0] = (float)((double)(long long)tot / (double)Q_SCALE);
        }
    }
}

// ---------------------------------------------------------------------------
extern "C" void kernel_launch(void* const* d_in, const int* in_sizes, int n_in,
                              void* d_out, int out_size) {
    const float* true_latent = (const float*)d_in[0];   // [B,T,F]
    const float* ctx         = (const float*)d_in[1];   // [B,T,C]
    const float* Wl          = (const float*)d_in[2];   // [F,C]
    const float* bl          = (const float*)d_in[3];   // [C]
    const float* Ws          = (const float*)d_in[4];   // [12]
    const float* bs          = (const float*)d_in[5];   // [12]
    const int*   neg         = (const int*)d_in[6];     // [B,NEG,T]
    float* out = (float*)d_out;

    cudaFuncSetAttribute(gemm_tl_tc, cudaFuncAttributeMaxDynamicSharedMemorySize,
                         (int)DYN_SM);
    cudaFuncSetAttribute(loss_kernel, cudaFuncAttributeMaxDynamicSharedMemorySize,
                         (int)DYN_LOSS);

    convert_bf16<<<2048, 256>>>(true_latent, Wl);
    gemm_tl_tc<<<dim3(C_ / 128, (B_ * T_) / 64), 256, DYN_SM>>>(bl);
    loss_kernel<<<dim3(T_ / UB_, B_), 256, DYN_LOSS>>>(ctx, Ws, bs, neg, out);
}